// round 15
// baseline (speedup 1.0000x reference)
#include <cuda_runtime.h>
#include <cuda_fp16.h>
#include <cstdint>
#include <cstddef>

// Problem constants
#define B_  16
#define C1_ 128
#define C2_ 256
#define H_  80
#define W_  80
#define P_  (H_*W_)           // 6400
#define EPS_ 1e-5f

// k5 A layout: [b][og2][chunk16][o128][144]  (chunk = 16-ci block, k = q*16+ci_sub)
#define K5_CH 16
#define K5_K  144
#define ACH   152             // A smem row stride (halves) - bank-conflict free
#define BROW  40              // B smem row stride (halves) - bank-conflict free
// 12x16 px tile -> 14x18 halo = 252 px
#define K5_HALO 252
#define K5_SMEM (128*ACH*2 + K5_HALO*BROW*2)   // 38912 + 20160 = 59072

// Scratch (device globals)
__device__ float g_ps [B_*C2_*128];       // [tile][b*C2+o] partial sums (50 tiles)
__device__ float g_ps2[B_*C2_*128];
__device__ float g_mu[B_*C2_];
__device__ float g_rstd[B_*C2_];
__device__ float g_attn[B_*4];
__device__ float g_aggb[B_*C2_];
__device__ float g_cq [B_*C2_*9];
__device__ float g_cqt[B_*C2_];
// MMA weights (rstd-folded fp16): [b][og2][chunk16][o128][144]  (~18.9 MB)
__device__ __align__(16) __half g_wm[(size_t)B_*2*K5_CH*128*K5_K];
// MMA input y (fp16): [b][pix6400][ci256] (~52 MB)
__device__ __align__(16) __half g_ym[(size_t)B_*P_*C2_];

__device__ __forceinline__ void mma16816(float* d, const uint32_t* a, const uint32_t* bb)
{
    asm volatile(
        "mma.sync.aligned.m16n8k16.row.col.f32.f16.f16.f32 "
        "{%0,%1,%2,%3}, {%4,%5,%6,%7}, {%8,%9}, {%0,%1,%2,%3};"
        : "+f"(d[0]), "+f"(d[1]), "+f"(d[2]), "+f"(d[3])
        : "r"(a[0]), "r"(a[1]), "r"(a[2]), "r"(a[3]), "r"(bb[0]), "r"(bb[1]));
}

// ---------------------------------------------------------------------------
// K1: conv1x1 + bn + silu via 1-pass fp16 mma.sync
// ---------------------------------------------------------------------------
__global__ __launch_bounds__(256)
void k1_mma(const float* __restrict__ x, const float* __restrict__ w,
            const float* __restrict__ bng, const float* __restrict__ bnb,
            const float* __restrict__ bnm, const float* __restrict__ bnv)
{
    __shared__ __align__(16) union {
        struct { __half Ah[5120], Bh[5120]; } st;   // 20 KB
        __half outb[128*136];                        // 34.8 KB
    } u;
    __shared__ float wsum[2][128], wsum2[2][128];

    const int b  = blockIdx.z;
    const int og = blockIdx.y;
    const int p0 = blockIdx.x * 128;
    const int tid = threadIdx.x;
    const int lane = tid & 31, warp = tid >> 5;
    const int warp_m = warp & 3, warp_n = warp >> 2;
    const int px_l = tid & 127, cblk = tid >> 7;

    float acc[2][8][4];
#pragma unroll
    for (int mr = 0; mr < 2; ++mr)
#pragma unroll
        for (int nr = 0; nr < 8; ++nr)
#pragma unroll
            for (int j = 0; j < 4; ++j) acc[mr][nr][j] = 0.f;

    for (int ch = 0; ch < 4; ++ch) {
#pragma unroll
        for (int it = 0; it < 16; ++it) {
            int idx = tid + 256*it;              // < 4096
            int o = idx >> 5, c = idx & 31;
            u.st.Ah[o*40 + c] = __float2half_rn(w[(og*128+o)*C1_ + ch*32 + c]);
        }
        __half hbuf[16];
#pragma unroll
        for (int j = 0; j < 16; ++j)
            hbuf[j] = __float2half_rn(
                x[((size_t)(b*C1_ + ch*32 + cblk*16 + j))*P_ + p0 + px_l]);
        *(int4*)&u.st.Bh[px_l*40 + cblk*16]     = ((int4*)hbuf)[0];
        *(int4*)&u.st.Bh[px_l*40 + cblk*16 + 8] = ((int4*)hbuf)[1];
        __syncthreads();

#pragma unroll
        for (int ks = 0; ks < 2; ++ks) {
            const int kb = ks*16 + 2*(lane&3);
            uint32_t ah[2][4];
#pragma unroll
            for (int mr = 0; mr < 2; ++mr) {
                int o = warp_m*32 + mr*16 + (lane>>2);
                const uint32_t* ph  = (const uint32_t*)&u.st.Ah[o*40 + kb];
                const uint32_t* ph8 = (const uint32_t*)&u.st.Ah[(o+8)*40 + kb];
                ah[mr][0] = ph[0];  ah[mr][1] = ph8[0];  ah[mr][2] = ph[4];  ah[mr][3] = ph8[4];
            }
            uint32_t bh[8][2];
#pragma unroll
            for (int nr = 0; nr < 8; ++nr) {
                int px = warp_n*64 + nr*8 + (lane>>2);
                const uint32_t* qh = (const uint32_t*)&u.st.Bh[px*40 + ks*16 + 2*(lane&3)];
                bh[nr][0] = qh[0];  bh[nr][1] = qh[4];
            }
#pragma unroll
            for (int mr = 0; mr < 2; ++mr)
#pragma unroll
                for (int nr = 0; nr < 8; ++nr)
                    mma16816(acc[mr][nr], ah[mr], bh[nr]);
        }
        __syncthreads();
    }

    // Epilogue: bn + silu (fp32), partial sums, fp16 staging [px][o]
#pragma unroll
    for (int mr = 0; mr < 2; ++mr) {
        const int ola = warp_m*32 + mr*16 + (lane>>2);
        const int olb = ola + 8;
        const int o_a = og*128 + ola, o_b = og*128 + olb;
        float sa = bng[o_a] * rsqrtf(bnv[o_a] + EPS_);
        float ta = bnb[o_a] - bnm[o_a]*sa;
        float sb = bng[o_b] * rsqrtf(bnv[o_b] + EPS_);
        float tb = bnb[o_b] - bnm[o_b]*sb;
        float sA = 0.f, sA2 = 0.f, sB = 0.f, sB2 = 0.f;
#pragma unroll
        for (int nr = 0; nr < 8; ++nr) {
#pragma unroll
            for (int c = 0; c < 2; ++c) {
                int px = warp_n*64 + nr*8 + 2*(lane&3) + c;
                float va = acc[mr][nr][c]*sa + ta;
                va = va / (1.f + expf(-va));
                sA += va; sA2 += va*va;
                u.outb[px*136 + ola] = __float2half_rn(va);
                float vb = acc[mr][nr][2+c]*sb + tb;
                vb = vb / (1.f + expf(-vb));
                sB += vb; sB2 += vb*vb;
                u.outb[px*136 + olb] = __float2half_rn(vb);
            }
        }
#pragma unroll
        for (int off = 1; off <= 2; off <<= 1) {
            sA  += __shfl_xor_sync(0xffffffffu, sA,  off);
            sA2 += __shfl_xor_sync(0xffffffffu, sA2, off);
            sB  += __shfl_xor_sync(0xffffffffu, sB,  off);
            sB2 += __shfl_xor_sync(0xffffffffu, sB2, off);
        }
        if ((lane & 3) == 0) {
            wsum [warp_n][ola] = sA;  wsum2[warp_n][ola] = sA2;
            wsum [warp_n][olb] = sB;  wsum2[warp_n][olb] = sB2;
        }
    }
    __syncthreads();
    if (tid < 128) {
        float s  = wsum [0][tid] + wsum [1][tid];
        float s2 = wsum2[0][tid] + wsum2[1][tid];
        g_ps [blockIdx.x*(B_*C2_) + b*C2_ + og*128 + tid] = s;
        g_ps2[blockIdx.x*(B_*C2_) + b*C2_ + og*128 + tid] = s2;
    }
#pragma unroll
    for (int it = 0; it < 8; ++it) {
        int l = tid + 256*it;
        int px = l >> 4, seg = l & 15;
        *(int4*)(g_ym + ((size_t)b*P_ + p0 + px)*C2_ + og*128 + seg*8) =
            *(const int4*)&u.outb[px*136 + seg*8];
    }
}

// ---------------------------------------------------------------------------
// K2: finalize stats + fused attention (one block per sample)
// ---------------------------------------------------------------------------
__global__ __launch_bounds__(256)
void k2_fin(const float* __restrict__ fc1w, const float* __restrict__ fc1b,
            const float* __restrict__ fc2w, const float* __restrict__ fc2b)
{
    __shared__ float pooled[256];
    const int b = blockIdx.x, o = threadIdx.x;
    const int idx = b*C2_ + o;
    float s = 0.f, s2 = 0.f;
    for (int t = 0; t < 50; ++t) {
        s  += g_ps [t*(B_*C2_) + idx];
        s2 += g_ps2[t*(B_*C2_) + idx];
    }
    float mu  = s  * (1.f / P_);
    float var = s2 * (1.f / P_) - mu*mu;
    float rs  = rsqrtf(fmaxf(var, 0.f) + EPS_);
    g_mu[idx]   = mu;
    g_rstd[idx] = rs;
    pooled[o] = mu;
    __syncthreads();

    if (o < 32) {
        const int lane = o;
        float s0 = 0.f, s1 = 0.f, s2a = 0.f, s3 = 0.f;
        for (int c = lane; c < C2_; c += 32) {
            float pv = pooled[c];
            s0  += pv * fc1w[0*C2_ + c];
            s1  += pv * fc1w[1*C2_ + c];
            s2a += pv * fc1w[2*C2_ + c];
            s3  += pv * fc1w[3*C2_ + c];
        }
#pragma unroll
        for (int off = 16; off; off >>= 1) {
            s0  += __shfl_down_sync(0xffffffffu, s0,  off);
            s1  += __shfl_down_sync(0xffffffffu, s1,  off);
            s2a += __shfl_down_sync(0xffffffffu, s2a, off);
            s3  += __shfl_down_sync(0xffffffffu, s3,  off);
        }
        if (lane == 0) {
            float a[4];
            a[0] = fmaxf(s0  + fc1b[0], 0.f);
            a[1] = fmaxf(s1  + fc1b[1], 0.f);
            a[2] = fmaxf(s2a + fc1b[2], 0.f);
            a[3] = fmaxf(s3  + fc1b[3], 0.f);
            float l[4];
#pragma unroll
            for (int j = 0; j < 4; ++j)
                l[j] = a[0]*fc2w[j*4+0] + a[1]*fc2w[j*4+1] + a[2]*fc2w[j*4+2] + a[3]*fc2w[j*4+3] + fc2b[j];
            float m = fmaxf(fmaxf(l[0], l[1]), fmaxf(l[2], l[3]));
            float e[4], den = 0.f;
#pragma unroll
            for (int j = 0; j < 4; ++j) { e[j] = expf(l[j] - m); den += e[j]; }
            float inv = 1.f / den;
#pragma unroll
            for (int j = 0; j < 4; ++j) g_attn[b*4 + j] = e[j] * inv;
        }
    }
}

// ---------------------------------------------------------------------------
// K4: aggregate weights, fold rstd, emit k5 A layout [chunk][o][q*16+ci_sub]
// ---------------------------------------------------------------------------
__global__ __launch_bounds__(256)
void k4_aggw(const float* __restrict__ dyw)
{
    __shared__ float s[128*73];
    const int ch = blockIdx.x, og = blockIdx.y, b = blockIdx.z;
    const int tid = threadIdx.x;
    const float a0 = g_attn[b*4+0], a1 = g_attn[b*4+1];
    const float a2 = g_attn[b*4+2], a3 = g_attn[b*4+3];
    const size_t ks = (size_t)C2_*C2_*9;

#pragma unroll
    for (int i = 0; i < 36; ++i) {
        int idx = tid + 256*i;                    // < 9216
        int o = idx / 72, r = idx - o*72;         // r = ci_sub*9 + q
        size_t base = (size_t)(og*128 + o)*2304 + ch*72 + r;
        float v = a0*dyw[base] + a1*dyw[base+ks] + a2*dyw[base+2*ks] + a3*dyw[base+3*ks];
        int ci = ch*8 + r/9;
        v *= g_rstd[b*C2_ + ci];
        s[o*73 + r] = v;
    }
    __syncthreads();

    __half* obase = g_wm + ((size_t)(b*2 + og)*K5_CH + (ch>>1))*(size_t)(128*K5_K)
                  + (ch&1)*8;
#pragma unroll
    for (int i = 0; i < 5; ++i) {
        int idx = tid + 256*i;                    // < 1152 = 128 o * 9 q
        if (idx < 1152) {
            int o = idx & 127, q = idx >> 7;
            alignas(16) __half hv[8];
#pragma unroll
            for (int cs = 0; cs < 8; ++cs)
                hv[cs] = __float2half_rn(s[o*73 + cs*9 + q]);
            *(int4*)(obase + o*K5_K + q*16) = *(const int4*)hv;
        }
    }
}

// K4c: Cq[b,o,q] from the fp16 aggregated weights (rstd folded) + Cqt + agg_b
__global__ __launch_bounds__(288)
void k4c_cq(const float* __restrict__ dyb)
{
    __shared__ float sh[32][9];
    __shared__ float shc[9];
    const int o = blockIdx.x, b = blockIdx.y;
    const int tid = threadIdx.x;
    const int ciw = tid / 9, q = tid - ciw*9;
    const int og = o >> 7, ol = o & 127;

    float acc = 0.f;
    if (tid < 288) {
        const __half* wb = g_wm + (size_t)(b*2 + og)*K5_CH*(size_t)(128*K5_K)
                         + (size_t)ol*K5_K + q*16;
#pragma unroll
        for (int j = 0; j < 8; ++j) {
            int ci = ciw + 32*j;
            int ch = ci >> 4, sub = ci & 15;
            acc += __half2float(wb[(size_t)ch*(128*K5_K) + sub]) * g_mu[b*C2_ + ci];
        }
    }
    sh[ciw][q] = acc;
    __syncthreads();
    if (tid < 9) {
        float sum = 0.f;
#pragma unroll
        for (int i = 0; i < 32; ++i) sum += sh[i][tid];
        g_cq[(b*C2_+o)*9 + tid] = sum;
        shc[tid] = sum;
    }
    __syncthreads();
    if (tid == 0) {
        float sum = 0.f;
#pragma unroll
        for (int i = 0; i < 9; ++i) sum += shc[i];
        g_cqt[b*C2_+o] = sum;
        const float a0 = g_attn[b*4+0], a1 = g_attn[b*4+1];
        const float a2 = g_attn[b*4+2], a3 = g_attn[b*4+3];
        g_aggb[b*C2_+o] = a0*dyb[0*C2_+o] + a1*dyb[1*C2_+o]
                        + a2*dyb[2*C2_+o] + a3*dyb[3*C2_+o];
    }
}

// ---------------------------------------------------------------------------
// K5: implicit-GEMM 3x3 conv, 1-pass fp16 mma.sync.
// EXPERIMENT: 384 threads = 12 warps = 3 warps/SMSP (clean, no reg cap issue:
// limit 168 vs ~110 used). Tile: 128 o x 192 px (12x16); last row-band (h0=72)
// computes 4 garbage rows, stores guarded (5% compute waste).
// K = 16 chunks x (9 taps x 16 ci) -> 144 k16-steps.
// ---------------------------------------------------------------------------
__global__ __launch_bounds__(384)
void k5_mma(const float* __restrict__ g1, const float* __restrict__ b1,
            const float* __restrict__ m1, const float* __restrict__ v1,
            float* __restrict__ out)
{
    extern __shared__ __align__(16) __half sm5[];
    __half* const As = sm5;                 // [128][ACH=152]
    __half* const Bs = sm5 + 128*ACH;       // [252][BROW=40]

    const int b    = blockIdx.z;
    const int og   = blockIdx.y;
    const int tile = blockIdx.x;                 // 0..34
    const int h0 = (tile/5)*12, w0 = (tile%5)*16;
    const int tid  = threadIdx.x;
    const int lane = tid & 31, warp = tid >> 5;
    const int warp_m = warp & 3, warp_n = warp >> 2;   // 4 x 3

    float acc[2][8][4];
#pragma unroll
    for (int mr = 0; mr < 2; ++mr)
#pragma unroll
        for (int nr = 0; nr < 8; ++nr)
#pragma unroll
            for (int j = 0; j < 4; ++j) acc[mr][nr][j] = 0.f;

    const __half* wsrc = g_wm + (size_t)(b*2 + og)*K5_CH*(size_t)(128*K5_K);

    // B staging: threads 0..251, one halo pixel each (14x18 halo), 16 ci = 2 int4
    const int st_px = tid;
    const int st_r = st_px/18, st_c = st_px - st_r*18;
    const int gh = h0 + st_r - 1, gw = w0 + st_c - 1;
    const bool st_ok = (tid < K5_HALO) && gh >= 0 && gh < H_ && gw >= 0 && gw < W_;
    const int ghc = max(0, min(H_-1, gh)), gwc = max(0, min(W_-1, gw));
    const size_t st_src0 = ((size_t)b*P_ + ghc*W_ + gwc)*(size_t)C2_;

    for (int ch = 0; ch < K5_CH; ++ch) {
        // stage A: 128 o x 144 k (36.9KB) -> rows restrided to ACH; 2304 int4 / 384 thr
        {
            const int4* asrc = (const int4*)(wsrc + (size_t)ch*(128*K5_K));
            int4* adst = (int4*)As;
#pragma unroll
            for (int i = 0; i < 6; ++i) {
                int idx = tid + 384*i;            // < 2304
                int o = idx / 18, j = idx - o*18;
                adst[o*19 + j] = asrc[idx];
            }
        }
        // stage B: halo pixels x 16 ci of this chunk
        if (tid < K5_HALO) {
            int4 v0 = make_int4(0,0,0,0), v1 = make_int4(0,0,0,0);
            if (st_ok) {
                const int4* src = (const int4*)(g_ym + st_src0 + ch*16);
                v0 = src[0]; v1 = src[1];
            }
            *(int4*)&Bs[st_px*BROW]     = v0;
            *(int4*)&Bs[st_px*BROW + 8] = v1;
        }
        __syncthreads();

#pragma unroll
        for (int s = 0; s < 9; ++s) {             // s = tap q
            const int dy = s/3, dx = s - (s/3)*3; // 0..2
            uint32_t ah[2][4];
            const int kb = s*16 + 2*(lane&3);
#pragma unroll
            for (int mr = 0; mr < 2; ++mr) {
                int o = warp_m*32 + mr*16 + (lane>>2);
                const uint32_t* ph  = (const uint32_t*)&As[o*ACH + kb];
                const uint32_t* ph8 = (const uint32_t*)&As[(o+8)*ACH + kb];
                ah[mr][0] = ph[0];  ah[mr][1] = ph8[0];  ah[mr][2] = ph[4];  ah[mr][3] = ph8[4];
            }
            uint32_t bh[8][2];
#pragma unroll
            for (int nr = 0; nr < 8; ++nr) {
                int pr = warp_n*4 + (nr>>1);
                int pc = (nr&1)*8 + (lane>>2);
                const uint32_t* q32 =
                    (const uint32_t*)&Bs[((pr+dy)*18 + pc+dx)*BROW + 2*(lane&3)];
                bh[nr][0] = q32[0];
                bh[nr][1] = q32[4];
            }
#pragma unroll
            for (int mr = 0; mr < 2; ++mr)
#pragma unroll
                for (int nr = 0; nr < 8; ++nr)
                    mma16816(acc[mr][nr], ah[mr], bh[nr]);
        }
        __syncthreads();
    }

    // Epilogue: res = (acc + borderfix)*s + ((aggb - Cqt - m1)*s + b1); guard h < H
    const int obase = og*128 + warp_m*32;
#pragma unroll
    for (int mr = 0; mr < 2; ++mr) {
        const int o_a = obase + mr*16 + (lane>>2);
        const int o_b = o_a + 8;
        float sA = __ldg(&g1[o_a]) * rsqrtf(__ldg(&v1[o_a]) + EPS_);
        float offA = (__ldg(&g_aggb[b*C2_+o_a]) - g_cqt[b*C2_+o_a] - __ldg(&m1[o_a]))*sA + __ldg(&b1[o_a]);
        float sB = __ldg(&g1[o_b]) * rsqrtf(__ldg(&v1[o_b]) + EPS_);
        float offB = (__ldg(&g_aggb[b*C2_+o_b]) - g_cqt[b*C2_+o_b] - __ldg(&m1[o_b]))*sB + __ldg(&b1[o_b]);
#pragma unroll
        for (int nr = 0; nr < 8; ++nr) {
            int pr = warp_n*4 + (nr>>1);
            int pc = (nr&1)*8 + 2*(lane&3);
            int h = h0 + pr, w1 = w0 + pc, w2 = w1 + 1;
            if (h >= H_) continue;
            float fA1 = 0.f, fA2 = 0.f, fB1 = 0.f, fB2 = 0.f;
            if (h == 0 || h == H_-1 || w1 == 0 || w2 == W_-1) {
#pragma unroll
                for (int q = 0; q < 9; ++q) {
                    int dy = q/3 - 1, dx = q - (q/3)*3 - 1;
                    bool ro = (unsigned)(h+dy) >= (unsigned)H_;
                    bool c1 = ro || (unsigned)(w1+dx) >= (unsigned)W_;
                    bool c2 = ro || (unsigned)(w2+dx) >= (unsigned)W_;
                    if (c1 | c2) {
                        float ca = g_cq[(b*C2_+o_a)*9 + q];
                        float cb = g_cq[(b*C2_+o_b)*9 + q];
                        if (c1) { fA1 += ca; fB1 += cb; }
                        if (c2) { fA2 += ca; fB2 += cb; }
                    }
                }
            }
            size_t po = (size_t)h*W_ + w1;
            float2 vA, vB;
            vA.x = (acc[mr][nr][0]+fA1)*sA + offA;  vA.y = (acc[mr][nr][1]+fA2)*sA + offA;
            vB.x = (acc[mr][nr][2]+fB1)*sB + offB;  vB.y = (acc[mr][nr][3]+fB2)*sB + offB;
            *(float2*)&out[((size_t)(b*C2_+o_a))*P_ + po] = vA;
            *(float2*)&out[((size_t)(b*C2_+o_b))*P_ + po] = vB;
        }
    }
}

// ---------------------------------------------------------------------------
extern "C" void kernel_launch(void* const* d_in, const int* in_sizes, int n_in,
                              void* d_out, int out_size)
{
    const float* x      = (const float*)d_in[0];
    const float* conv1w = (const float*)d_in[1];
    const float* bng    = (const float*)d_in[2];
    const float* bnb    = (const float*)d_in[3];
    const float* bnm    = (const float*)d_in[4];
    const float* bnv    = (const float*)d_in[5];
    const float* fc1w   = (const float*)d_in[6];
    const float* fc1b   = (const float*)d_in[7];
    const float* fc2w   = (const float*)d_in[8];
    const float* fc2b   = (const float*)d_in[9];
    const float* dyw    = (const float*)d_in[10];
    const float* dyb    = (const float*)d_in[11];
    const float* g1     = (const float*)d_in[12];
    const float* b1     = (const float*)d_in[13];
    const float* m1     = (const float*)d_in[14];
    const float* v1     = (const float*)d_in[15];
    float* out = (float*)d_out;

    cudaFuncSetAttribute(k5_mma, cudaFuncAttributeMaxDynamicSharedMemorySize, K5_SMEM);

    k1_mma<<<dim3(50, 2, B_), 256>>>(x, conv1w, bng, bnb, bnm, bnv);
    k2_fin<<<B_, 256>>>(fc1w, fc1b, fc2w, fc2b);
    k4_aggw<<<dim3(32, 2, B_), 256>>>(dyw);
    k4c_cq<<<dim3(C2_, B_), 288>>>(dyb);
    k5_mma<<<dim3(35, 2, B_), 384, K5_SMEM>>>(g1, b1, m1, v1, out);
}

// round 16
// speedup vs baseline: 1.1890x; 1.1890x over previous
#include <cuda_runtime.h>
#include <cuda_fp16.h>
#include <cstdint>
#include <cstddef>

// Problem constants
#define B_  16
#define C1_ 128
#define C2_ 256
#define H_  80
#define W_  80
#define P_  (H_*W_)           // 6400
#define EPS_ 1e-5f

// k5 A layout: [b][og2][chunk16][o128][144]  (chunk = 16-ci block, k = q*16+ci_sub)
#define K5_CH 16
#define K5_K  144
#define ACH   152             // A smem row stride (halves) - bank-conflict free
#define BROW  40              // B smem row stride (halves) - bank-conflict free
#define K5_SMEM (128*ACH*2 + 180*BROW*2)   // 38912 + 14400 = 53312

// Scratch (device globals)
__device__ float g_ps [B_*C2_*128];       // [tile][b*C2+o] partial sums (50 tiles)
__device__ float g_ps2[B_*C2_*128];
__device__ float g_mu[B_*C2_];
__device__ float g_rstd[B_*C2_];
__device__ float g_attn[B_*4];
__device__ float g_aggb[B_*C2_];
__device__ float g_cq [B_*C2_*9];
__device__ float g_cqt[B_*C2_];
// MMA weights (rstd-folded fp16): [b][og2][chunk16][o128][144]  (~18.9 MB)
__device__ __align__(16) __half g_wm[(size_t)B_*2*K5_CH*128*K5_K];
// MMA input y (fp16): [b][pix6400][ci256] (~52 MB)
__device__ __align__(16) __half g_ym[(size_t)B_*P_*C2_];

__device__ __forceinline__ void mma16816(float* d, const uint32_t* a, const uint32_t* bb)
{
    asm volatile(
        "mma.sync.aligned.m16n8k16.row.col.f32.f16.f16.f32 "
        "{%0,%1,%2,%3}, {%4,%5,%6,%7}, {%8,%9}, {%0,%1,%2,%3};"
        : "+f"(d[0]), "+f"(d[1]), "+f"(d[2]), "+f"(d[3])
        : "r"(a[0]), "r"(a[1]), "r"(a[2]), "r"(a[3]), "r"(bb[0]), "r"(bb[1]));
}

// ---------------------------------------------------------------------------
// K1: conv1x1 + bn + silu via 1-pass fp16 mma.sync
//     tile: 128 o x 128 px, K=128 in 4 chunks of 32. 8 warps = 4M x 2N.
//     Writes fp16 g_ym[b][px][ci] + fp32 partial sums for InstanceNorm stats.
// ---------------------------------------------------------------------------
__global__ __launch_bounds__(256)
void k1_mma(const float* __restrict__ x, const float* __restrict__ w,
            const float* __restrict__ bng, const float* __restrict__ bnb,
            const float* __restrict__ bnm, const float* __restrict__ bnv)
{
    __shared__ __align__(16) union {
        struct { __half Ah[5120], Bh[5120]; } st;   // 20 KB
        __half outb[128*136];                        // 34.8 KB
    } u;
    __shared__ float wsum[2][128], wsum2[2][128];

    const int b  = blockIdx.z;
    const int og = blockIdx.y;
    const int p0 = blockIdx.x * 128;
    const int tid = threadIdx.x;
    const int lane = tid & 31, warp = tid >> 5;
    const int warp_m = warp & 3, warp_n = warp >> 2;
    const int px_l = tid & 127, cblk = tid >> 7;

    float acc[2][8][4];
#pragma unroll
    for (int mr = 0; mr < 2; ++mr)
#pragma unroll
        for (int nr = 0; nr < 8; ++nr)
#pragma unroll
            for (int j = 0; j < 4; ++j) acc[mr][nr][j] = 0.f;

    for (int ch = 0; ch < 4; ++ch) {
#pragma unroll
        for (int it = 0; it < 16; ++it) {
            int idx = tid + 256*it;              // < 4096
            int o = idx >> 5, c = idx & 31;
            u.st.Ah[o*40 + c] = __float2half_rn(w[(og*128+o)*C1_ + ch*32 + c]);
        }
        __half hbuf[16];
#pragma unroll
        for (int j = 0; j < 16; ++j)
            hbuf[j] = __float2half_rn(
                x[((size_t)(b*C1_ + ch*32 + cblk*16 + j))*P_ + p0 + px_l]);
        *(int4*)&u.st.Bh[px_l*40 + cblk*16]     = ((int4*)hbuf)[0];
        *(int4*)&u.st.Bh[px_l*40 + cblk*16 + 8] = ((int4*)hbuf)[1];
        __syncthreads();

#pragma unroll
        for (int ks = 0; ks < 2; ++ks) {
            const int kb = ks*16 + 2*(lane&3);
            uint32_t ah[2][4];
#pragma unroll
            for (int mr = 0; mr < 2; ++mr) {
                int o = warp_m*32 + mr*16 + (lane>>2);
                const uint32_t* ph  = (const uint32_t*)&u.st.Ah[o*40 + kb];
                const uint32_t* ph8 = (const uint32_t*)&u.st.Ah[(o+8)*40 + kb];
                ah[mr][0] = ph[0];  ah[mr][1] = ph8[0];  ah[mr][2] = ph[4];  ah[mr][3] = ph8[4];
            }
            uint32_t bh[8][2];
#pragma unroll
            for (int nr = 0; nr < 8; ++nr) {
                int px = warp_n*64 + nr*8 + (lane>>2);
                const uint32_t* qh = (const uint32_t*)&u.st.Bh[px*40 + ks*16 + 2*(lane&3)];
                bh[nr][0] = qh[0];  bh[nr][1] = qh[4];
            }
#pragma unroll
            for (int mr = 0; mr < 2; ++mr)
#pragma unroll
                for (int nr = 0; nr < 8; ++nr)
                    mma16816(acc[mr][nr], ah[mr], bh[nr]);
        }
        __syncthreads();
    }

    // Epilogue: bn + silu (fp32), partial sums, fp16 staging [px][o]
#pragma unroll
    for (int mr = 0; mr < 2; ++mr) {
        const int ola = warp_m*32 + mr*16 + (lane>>2);
        const int olb = ola + 8;
        const int o_a = og*128 + ola, o_b = og*128 + olb;
        float sa = bng[o_a] * rsqrtf(bnv[o_a] + EPS_);
        float ta = bnb[o_a] - bnm[o_a]*sa;
        float sb = bng[o_b] * rsqrtf(bnv[o_b] + EPS_);
        float tb = bnb[o_b] - bnm[o_b]*sb;
        float sA = 0.f, sA2 = 0.f, sB = 0.f, sB2 = 0.f;
#pragma unroll
        for (int nr = 0; nr < 8; ++nr) {
#pragma unroll
            for (int c = 0; c < 2; ++c) {
                int px = warp_n*64 + nr*8 + 2*(lane&3) + c;
                float va = acc[mr][nr][c]*sa + ta;
                va = va / (1.f + expf(-va));
                sA += va; sA2 += va*va;
                u.outb[px*136 + ola] = __float2half_rn(va);
                float vb = acc[mr][nr][2+c]*sb + tb;
                vb = vb / (1.f + expf(-vb));
                sB += vb; sB2 += vb*vb;
                u.outb[px*136 + olb] = __float2half_rn(vb);
            }
        }
#pragma unroll
        for (int off = 1; off <= 2; off <<= 1) {
            sA  += __shfl_xor_sync(0xffffffffu, sA,  off);
            sA2 += __shfl_xor_sync(0xffffffffu, sA2, off);
            sB  += __shfl_xor_sync(0xffffffffu, sB,  off);
            sB2 += __shfl_xor_sync(0xffffffffu, sB2, off);
        }
        if ((lane & 3) == 0) {
            wsum [warp_n][ola] = sA;  wsum2[warp_n][ola] = sA2;
            wsum [warp_n][olb] = sB;  wsum2[warp_n][olb] = sB2;
        }
    }
    __syncthreads();
    if (tid < 128) {
        float s  = wsum [0][tid] + wsum [1][tid];
        float s2 = wsum2[0][tid] + wsum2[1][tid];
        g_ps [blockIdx.x*(B_*C2_) + b*C2_ + og*128 + tid] = s;
        g_ps2[blockIdx.x*(B_*C2_) + b*C2_ + og*128 + tid] = s2;
    }
#pragma unroll
    for (int it = 0; it < 8; ++it) {
        int l = tid + 256*it;
        int px = l >> 4, seg = l & 15;
        *(int4*)(g_ym + ((size_t)b*P_ + p0 + px)*C2_ + og*128 + seg*8) =
            *(const int4*)&u.outb[px*136 + seg*8];
    }
}

// ---------------------------------------------------------------------------
// K2: finalize stats + fused attention (one block per sample)
// ---------------------------------------------------------------------------
__global__ __launch_bounds__(256)
void k2_fin(const float* __restrict__ fc1w, const float* __restrict__ fc1b,
            const float* __restrict__ fc2w, const float* __restrict__ fc2b)
{
    __shared__ float pooled[256];
    const int b = blockIdx.x, o = threadIdx.x;
    const int idx = b*C2_ + o;
    float s = 0.f, s2 = 0.f;
    for (int t = 0; t < 50; ++t) {
        s  += g_ps [t*(B_*C2_) + idx];
        s2 += g_ps2[t*(B_*C2_) + idx];
    }
    float mu  = s  * (1.f / P_);
    float var = s2 * (1.f / P_) - mu*mu;
    float rs  = rsqrtf(fmaxf(var, 0.f) + EPS_);
    g_mu[idx]   = mu;
    g_rstd[idx] = rs;
    pooled[o] = mu;
    __syncthreads();

    if (o < 32) {
        const int lane = o;
        float s0 = 0.f, s1 = 0.f, s2a = 0.f, s3 = 0.f;
        for (int c = lane; c < C2_; c += 32) {
            float pv = pooled[c];
            s0  += pv * fc1w[0*C2_ + c];
            s1  += pv * fc1w[1*C2_ + c];
            s2a += pv * fc1w[2*C2_ + c];
            s3  += pv * fc1w[3*C2_ + c];
        }
#pragma unroll
        for (int off = 16; off; off >>= 1) {
            s0  += __shfl_down_sync(0xffffffffu, s0,  off);
            s1  += __shfl_down_sync(0xffffffffu, s1,  off);
            s2a += __shfl_down_sync(0xffffffffu, s2a, off);
            s3  += __shfl_down_sync(0xffffffffu, s3,  off);
        }
        if (lane == 0) {
            float a[4];
            a[0] = fmaxf(s0  + fc1b[0], 0.f);
            a[1] = fmaxf(s1  + fc1b[1], 0.f);
            a[2] = fmaxf(s2a + fc1b[2], 0.f);
            a[3] = fmaxf(s3  + fc1b[3], 0.f);
            float l[4];
#pragma unroll
            for (int j = 0; j < 4; ++j)
                l[j] = a[0]*fc2w[j*4+0] + a[1]*fc2w[j*4+1] + a[2]*fc2w[j*4+2] + a[3]*fc2w[j*4+3] + fc2b[j];
            float m = fmaxf(fmaxf(l[0], l[1]), fmaxf(l[2], l[3]));
            float e[4], den = 0.f;
#pragma unroll
            for (int j = 0; j < 4; ++j) { e[j] = expf(l[j] - m); den += e[j]; }
            float inv = 1.f / den;
#pragma unroll
            for (int j = 0; j < 4; ++j) g_attn[b*4 + j] = e[j] * inv;
        }
    }
}

// ---------------------------------------------------------------------------
// K4: aggregate weights, fold rstd, emit k5 A layout [chunk][o][q*16+ci_sub]
// ---------------------------------------------------------------------------
__global__ __launch_bounds__(256)
void k4_aggw(const float* __restrict__ dyw)
{
    __shared__ float s[128*73];
    const int ch = blockIdx.x, og = blockIdx.y, b = blockIdx.z;
    const int tid = threadIdx.x;
    const float a0 = g_attn[b*4+0], a1 = g_attn[b*4+1];
    const float a2 = g_attn[b*4+2], a3 = g_attn[b*4+3];
    const size_t ks = (size_t)C2_*C2_*9;

#pragma unroll
    for (int i = 0; i < 36; ++i) {
        int idx = tid + 256*i;                    // < 9216
        int o = idx / 72, r = idx - o*72;         // r = ci_sub*9 + q
        size_t base = (size_t)(og*128 + o)*2304 + ch*72 + r;
        float v = a0*dyw[base] + a1*dyw[base+ks] + a2*dyw[base+2*ks] + a3*dyw[base+3*ks];
        int ci = ch*8 + r/9;
        v *= g_rstd[b*C2_ + ci];
        s[o*73 + r] = v;
    }
    __syncthreads();

    __half* obase = g_wm + ((size_t)(b*2 + og)*K5_CH + (ch>>1))*(size_t)(128*K5_K)
                  + (ch&1)*8;
#pragma unroll
    for (int i = 0; i < 5; ++i) {
        int idx = tid + 256*i;                    // < 1152 = 128 o * 9 q
        if (idx < 1152) {
            int o = idx & 127, q = idx >> 7;
            alignas(16) __half hv[8];
#pragma unroll
            for (int cs = 0; cs < 8; ++cs)
                hv[cs] = __float2half_rn(s[o*73 + cs*9 + q]);
            *(int4*)(obase + o*K5_K + q*16) = *(const int4*)hv;
        }
    }
}

// K4c: Cq[b,o,q] from the fp16 aggregated weights (rstd folded) + Cqt + agg_b
__global__ __launch_bounds__(288)
void k4c_cq(const float* __restrict__ dyb)
{
    __shared__ float sh[32][9];
    __shared__ float shc[9];
    const int o = blockIdx.x, b = blockIdx.y;
    const int tid = threadIdx.x;
    const int ciw = tid / 9, q = tid - ciw*9;
    const int og = o >> 7, ol = o & 127;

    float acc = 0.f;
    if (tid < 288) {
        const __half* wb = g_wm + (size_t)(b*2 + og)*K5_CH*(size_t)(128*K5_K)
                         + (size_t)ol*K5_K + q*16;
#pragma unroll
        for (int j = 0; j < 8; ++j) {
            int ci = ciw + 32*j;
            int ch = ci >> 4, sub = ci & 15;
            acc += __half2float(wb[(size_t)ch*(128*K5_K) + sub]) * g_mu[b*C2_ + ci];
        }
    }
    sh[ciw][q] = acc;
    __syncthreads();
    if (tid < 9) {
        float sum = 0.f;
#pragma unroll
        for (int i = 0; i < 32; ++i) sum += sh[i][tid];
        g_cq[(b*C2_+o)*9 + tid] = sum;
        shc[tid] = sum;
    }
    __syncthreads();
    if (tid == 0) {
        float sum = 0.f;
#pragma unroll
        for (int i = 0; i < 9; ++i) sum += shc[i];
        g_cqt[b*C2_+o] = sum;
        const float a0 = g_attn[b*4+0], a1 = g_attn[b*4+1];
        const float a2 = g_attn[b*4+2], a3 = g_attn[b*4+3];
        g_aggb[b*C2_+o] = a0*dyb[0*C2_+o] + a1*dyb[1*C2_+o]
                        + a2*dyb[2*C2_+o] + a3*dyb[3*C2_+o];
    }
}

// ---------------------------------------------------------------------------
// K5: implicit-GEMM 3x3 conv, 1-pass fp16 mma.sync (measured-best config:
// 256 threads/CTA -> 2 CTAs/SM resident = 4 warps/SMSP + cross-CTA overlap).
// K = 16 chunks x (9 taps x 16 ci) -> 144 k16-steps (minimum MMA count).
// Block: (b, og, 8x16-px tile). 8 warps = 4M x 2N.
// ---------------------------------------------------------------------------
__global__ __launch_bounds__(256)
void k5_mma(const float* __restrict__ g1, const float* __restrict__ b1,
            const float* __restrict__ m1, const float* __restrict__ v1,
            float* __restrict__ out)
{
    extern __shared__ __align__(16) __half sm5[];
    __half* const As = sm5;                 // [128][ACH=152]
    __half* const Bs = sm5 + 128*ACH;       // [180][BROW=40]

    const int b    = blockIdx.z;
    const int og   = blockIdx.y;
    const int tile = blockIdx.x;                 // 0..49
    const int h0 = (tile/5)*8, w0 = (tile%5)*16;
    const int tid  = threadIdx.x;
    const int lane = tid & 31, warp = tid >> 5;
    const int warp_m = warp & 3, warp_n = warp >> 2;

    float acc[2][8][4];
#pragma unroll
    for (int mr = 0; mr < 2; ++mr)
#pragma unroll
        for (int nr = 0; nr < 8; ++nr)
#pragma unroll
            for (int j = 0; j < 4; ++j) acc[mr][nr][j] = 0.f;

    const __half* wsrc = g_wm + (size_t)(b*2 + og)*K5_CH*(size_t)(128*K5_K);

    // B staging: threads 0..179, one halo pixel each (10x18 halo), 16 ci = 2 int4
    const int st_px = tid;
    const int st_r = st_px/18, st_c = st_px - st_r*18;
    const int gh = h0 + st_r - 1, gw = w0 + st_c - 1;
    const bool st_ok = (tid < 180) && gh >= 0 && gh < H_ && gw >= 0 && gw < W_;
    const int ghc = max(0, min(H_-1, gh)), gwc = max(0, min(W_-1, gw));
    const size_t st_src0 = ((size_t)b*P_ + ghc*W_ + gwc)*(size_t)C2_;

    for (int ch = 0; ch < K5_CH; ++ch) {
        // stage A: 128 o x 144 k (36.9KB) -> rows restrided to ACH
        {
            const int4* asrc = (const int4*)(wsrc + (size_t)ch*(128*K5_K));
            int4* adst = (int4*)As;
#pragma unroll
            for (int i = 0; i < 9; ++i) {
                int idx = tid + 256*i;            // < 2304
                int o = idx / 18, j = idx - o*18;
                adst[o*19 + j] = asrc[idx];
            }
        }
        // stage B: halo pixels x 16 ci of this chunk
        if (tid < 180) {
            int4 v0 = make_int4(0,0,0,0), v1 = make_int4(0,0,0,0);
            if (st_ok) {
                const int4* src = (const int4*)(g_ym + st_src0 + ch*16);
                v0 = src[0]; v1 = src[1];
            }
            *(int4*)&Bs[st_px*BROW]     = v0;
            *(int4*)&Bs[st_px*BROW + 8] = v1;
        }
        __syncthreads();

#pragma unroll
        for (int s = 0; s < 9; ++s) {             // s = tap q
            const int dy = s/3, dx = s - (s/3)*3; // 0..2
            uint32_t ah[2][4];
            const int kb = s*16 + 2*(lane&3);
#pragma unroll
            for (int mr = 0; mr < 2; ++mr) {
                int o = warp_m*32 + mr*16 + (lane>>2);
                const uint32_t* ph  = (const uint32_t*)&As[o*ACH + kb];
                const uint32_t* ph8 = (const uint32_t*)&As[(o+8)*ACH + kb];
                ah[mr][0] = ph[0];  ah[mr][1] = ph8[0];  ah[mr][2] = ph[4];  ah[mr][3] = ph8[4];
            }
            uint32_t bh[8][2];
#pragma unroll
            for (int nr = 0; nr < 8; ++nr) {
                int pr = warp_n*4 + (nr>>1);
                int pc = (nr&1)*8 + (lane>>2);
                const uint32_t* q32 =
                    (const uint32_t*)&Bs[((pr+dy)*18 + pc+dx)*BROW + 2*(lane&3)];
                bh[nr][0] = q32[0];
                bh[nr][1] = q32[4];
            }
#pragma unroll
            for (int mr = 0; mr < 2; ++mr)
#pragma unroll
                for (int nr = 0; nr < 8; ++nr)
                    mma16816(acc[mr][nr], ah[mr], bh[nr]);
        }
        __syncthreads();
    }

    // Epilogue: res = (acc + borderfix)*s + ((aggb - Cqt - m1)*s + b1)
    const int obase = og*128 + warp_m*32;
#pragma unroll
    for (int mr = 0; mr < 2; ++mr) {
        const int o_a = obase + mr*16 + (lane>>2);
        const int o_b = o_a + 8;
        float sA = __ldg(&g1[o_a]) * rsqrtf(__ldg(&v1[o_a]) + EPS_);
        float offA = (__ldg(&g_aggb[b*C2_+o_a]) - g_cqt[b*C2_+o_a] - __ldg(&m1[o_a]))*sA + __ldg(&b1[o_a]);
        float sB = __ldg(&g1[o_b]) * rsqrtf(__ldg(&v1[o_b]) + EPS_);
        float offB = (__ldg(&g_aggb[b*C2_+o_b]) - g_cqt[b*C2_+o_b] - __ldg(&m1[o_b]))*sB + __ldg(&b1[o_b]);
#pragma unroll
        for (int nr = 0; nr < 8; ++nr) {
            int pr = warp_n*4 + (nr>>1);
            int pc = (nr&1)*8 + 2*(lane&3);
            int h = h0 + pr, w1 = w0 + pc, w2 = w1 + 1;
            float fA1 = 0.f, fA2 = 0.f, fB1 = 0.f, fB2 = 0.f;
            if (h == 0 || h == H_-1 || w1 == 0 || w2 == W_-1) {
#pragma unroll
                for (int q = 0; q < 9; ++q) {
                    int dy = q/3 - 1, dx = q - (q/3)*3 - 1;
                    bool ro = (unsigned)(h+dy) >= (unsigned)H_;
                    bool c1 = ro || (unsigned)(w1+dx) >= (unsigned)W_;
                    bool c2 = ro || (unsigned)(w2+dx) >= (unsigned)W_;
                    if (c1 | c2) {
                        float ca = g_cq[(b*C2_+o_a)*9 + q];
                        float cb = g_cq[(b*C2_+o_b)*9 + q];
                        if (c1) { fA1 += ca; fB1 += cb; }
                        if (c2) { fA2 += ca; fB2 += cb; }
                    }
                }
            }
            size_t po = (size_t)h*W_ + w1;
            float2 vA, vB;
            vA.x = (acc[mr][nr][0]+fA1)*sA + offA;  vA.y = (acc[mr][nr][1]+fA2)*sA + offA;
            vB.x = (acc[mr][nr][2]+fB1)*sB + offB;  vB.y = (acc[mr][nr][3]+fB2)*sB + offB;
            *(float2*)&out[((size_t)(b*C2_+o_a))*P_ + po] = vA;
            *(float2*)&out[((size_t)(b*C2_+o_b))*P_ + po] = vB;
        }
    }
}

// ---------------------------------------------------------------------------
extern "C" void kernel_launch(void* const* d_in, const int* in_sizes, int n_in,
                              void* d_out, int out_size)
{
    const float* x      = (const float*)d_in[0];
    const float* conv1w = (const float*)d_in[1];
    const float* bng    = (const float*)d_in[2];
    const float* bnb    = (const float*)d_in[3];
    const float* bnm    = (const float*)d_in[4];
    const float* bnv    = (const float*)d_in[5];
    const float* fc1w   = (const float*)d_in[6];
    const float* fc1b   = (const float*)d_in[7];
    const float* fc2w   = (const float*)d_in[8];
    const float* fc2b   = (const float*)d_in[9];
    const float* dyw    = (const float*)d_in[10];
    const float* dyb    = (const float*)d_in[11];
    const float* g1     = (const float*)d_in[12];
    const float* b1     = (const float*)d_in[13];
    const float* m1     = (const float*)d_in[14];
    const float* v1     = (const float*)d_in[15];
    float* out = (float*)d_out;

    cudaFuncSetAttribute(k5_mma, cudaFuncAttributeMaxDynamicSharedMemorySize, K5_SMEM);

    k1_mma<<<dim3(50, 2, B_), 256>>>(x, conv1w, bng, bnb, bnm, bnv);
    k2_fin<<<B_, 256>>>(fc1w, fc1b, fc2w, fc2b);
    k4_aggw<<<dim3(32, 2, B_), 256>>>(dyw);
    k4c_cq<<<dim3(C2_, B_), 288>>>(dyb);
    k5_mma<<<dim3(50, 2, B_), 256, K5_SMEM>>>(g1, b1, m1, v1, out);
}

// round 17
// speedup vs baseline: 1.1965x; 1.0063x over previous
#include <cuda_runtime.h>
#include <cuda_fp16.h>
#include <cstdint>
#include <cstddef>

// Problem constants
#define B_  16
#define C1_ 128
#define C2_ 256
#define H_  80
#define W_  80
#define P_  (H_*W_)           // 6400
#define EPS_ 1e-5f

// k5 A layout: [b][og2][chunk16][o128][144]  (chunk = 16-ci block, k = q*16+ci_sub)
#define K5_CH 16
#define K5_K  144
#define ACH   152             // A smem row stride (halves) - bank-conflict free
#define BROW  40              // B smem row stride (halves) - bank-conflict free
#define K5_SMEM (128*ACH*2 + 180*BROW*2)   // 38912 + 14400 = 53312

// Scratch (device globals)
__device__ float g_ps [B_*C2_*128];       // [tile][b*C2+o] partial sums (50 tiles)
__device__ float g_ps2[B_*C2_*128];
__device__ float g_mu[B_*C2_];
__device__ float g_rstd[B_*C2_];
__device__ float g_attn[B_*4];
__device__ float g_aggb[B_*C2_];
__device__ float g_cq [B_*C2_*9];
__device__ float g_cqt[B_*C2_];
// MMA weights (rstd-folded fp16): [b][og2][chunk16][o128][144]  (~18.9 MB)
__device__ __align__(16) __half g_wm[(size_t)B_*2*K5_CH*128*K5_K];
// MMA input y (fp16): [b][pix6400][ci256] (~52 MB)
__device__ __align__(16) __half g_ym[(size_t)B_*P_*C2_];

__device__ __forceinline__ void mma16816(float* d, const uint32_t* a, const uint32_t* bb)
{
    asm volatile(
        "mma.sync.aligned.m16n8k16.row.col.f32.f16.f16.f32 "
        "{%0,%1,%2,%3}, {%4,%5,%6,%7}, {%8,%9}, {%0,%1,%2,%3};"
        : "+f"(d[0]), "+f"(d[1]), "+f"(d[2]), "+f"(d[3])
        : "r"(a[0]), "r"(a[1]), "r"(a[2]), "r"(a[3]), "r"(bb[0]), "r"(bb[1]));
}

// ---------------------------------------------------------------------------
// K1: conv1x1 + bn + silu via 1-pass fp16 mma.sync
//     tile: 128 o x 128 px, K=128 in 4 chunks of 32. 8 warps = 4M x 2N.
//     Writes fp16 g_ym[b][px][ci] + fp32 partial sums for InstanceNorm stats.
// ---------------------------------------------------------------------------
__global__ __launch_bounds__(256)
void k1_mma(const float* __restrict__ x, const float* __restrict__ w,
            const float* __restrict__ bng, const float* __restrict__ bnb,
            const float* __restrict__ bnm, const float* __restrict__ bnv)
{
    __shared__ __align__(16) union {
        struct { __half Ah[5120], Bh[5120]; } st;   // 20 KB
        __half outb[128*136];                        // 34.8 KB
    } u;
    __shared__ float wsum[2][128], wsum2[2][128];

    const int b  = blockIdx.z;
    const int og = blockIdx.y;
    const int p0 = blockIdx.x * 128;
    const int tid = threadIdx.x;
    const int lane = tid & 31, warp = tid >> 5;
    const int warp_m = warp & 3, warp_n = warp >> 2;
    const int px_l = tid & 127, cblk = tid >> 7;

    float acc[2][8][4];
#pragma unroll
    for (int mr = 0; mr < 2; ++mr)
#pragma unroll
        for (int nr = 0; nr < 8; ++nr)
#pragma unroll
            for (int j = 0; j < 4; ++j) acc[mr][nr][j] = 0.f;

    for (int ch = 0; ch < 4; ++ch) {
#pragma unroll
        for (int it = 0; it < 16; ++it) {
            int idx = tid + 256*it;              // < 4096
            int o = idx >> 5, c = idx & 31;
            u.st.Ah[o*40 + c] = __float2half_rn(w[(og*128+o)*C1_ + ch*32 + c]);
        }
        __half hbuf[16];
#pragma unroll
        for (int j = 0; j < 16; ++j)
            hbuf[j] = __float2half_rn(
                x[((size_t)(b*C1_ + ch*32 + cblk*16 + j))*P_ + p0 + px_l]);
        *(int4*)&u.st.Bh[px_l*40 + cblk*16]     = ((int4*)hbuf)[0];
        *(int4*)&u.st.Bh[px_l*40 + cblk*16 + 8] = ((int4*)hbuf)[1];
        __syncthreads();

#pragma unroll
        for (int ks = 0; ks < 2; ++ks) {
            const int kb = ks*16 + 2*(lane&3);
            uint32_t ah[2][4];
#pragma unroll
            for (int mr = 0; mr < 2; ++mr) {
                int o = warp_m*32 + mr*16 + (lane>>2);
                const uint32_t* ph  = (const uint32_t*)&u.st.Ah[o*40 + kb];
                const uint32_t* ph8 = (const uint32_t*)&u.st.Ah[(o+8)*40 + kb];
                ah[mr][0] = ph[0];  ah[mr][1] = ph8[0];  ah[mr][2] = ph[4];  ah[mr][3] = ph8[4];
            }
            uint32_t bh[8][2];
#pragma unroll
            for (int nr = 0; nr < 8; ++nr) {
                int px = warp_n*64 + nr*8 + (lane>>2);
                const uint32_t* qh = (const uint32_t*)&u.st.Bh[px*40 + ks*16 + 2*(lane&3)];
                bh[nr][0] = qh[0];  bh[nr][1] = qh[4];
            }
#pragma unroll
            for (int mr = 0; mr < 2; ++mr)
#pragma unroll
                for (int nr = 0; nr < 8; ++nr)
                    mma16816(acc[mr][nr], ah[mr], bh[nr]);
        }
        __syncthreads();
    }

    // Epilogue: bn + silu (fp32), partial sums, fp16 staging [px][o]
#pragma unroll
    for (int mr = 0; mr < 2; ++mr) {
        const int ola = warp_m*32 + mr*16 + (lane>>2);
        const int olb = ola + 8;
        const int o_a = og*128 + ola, o_b = og*128 + olb;
        float sa = bng[o_a] * rsqrtf(bnv[o_a] + EPS_);
        float ta = bnb[o_a] - bnm[o_a]*sa;
        float sb = bng[o_b] * rsqrtf(bnv[o_b] + EPS_);
        float tb = bnb[o_b] - bnm[o_b]*sb;
        float sA = 0.f, sA2 = 0.f, sB = 0.f, sB2 = 0.f;
#pragma unroll
        for (int nr = 0; nr < 8; ++nr) {
#pragma unroll
            for (int c = 0; c < 2; ++c) {
                int px = warp_n*64 + nr*8 + 2*(lane&3) + c;
                float va = acc[mr][nr][c]*sa + ta;
                va = va / (1.f + expf(-va));
                sA += va; sA2 += va*va;
                u.outb[px*136 + ola] = __float2half_rn(va);
                float vb = acc[mr][nr][2+c]*sb + tb;
                vb = vb / (1.f + expf(-vb));
                sB += vb; sB2 += vb*vb;
                u.outb[px*136 + olb] = __float2half_rn(vb);
            }
        }
#pragma unroll
        for (int off = 1; off <= 2; off <<= 1) {
            sA  += __shfl_xor_sync(0xffffffffu, sA,  off);
            sA2 += __shfl_xor_sync(0xffffffffu, sA2, off);
            sB  += __shfl_xor_sync(0xffffffffu, sB,  off);
            sB2 += __shfl_xor_sync(0xffffffffu, sB2, off);
        }
        if ((lane & 3) == 0) {
            wsum [warp_n][ola] = sA;  wsum2[warp_n][ola] = sA2;
            wsum [warp_n][olb] = sB;  wsum2[warp_n][olb] = sB2;
        }
    }
    __syncthreads();
    if (tid < 128) {
        float s  = wsum [0][tid] + wsum [1][tid];
        float s2 = wsum2[0][tid] + wsum2[1][tid];
        g_ps [blockIdx.x*(B_*C2_) + b*C2_ + og*128 + tid] = s;
        g_ps2[blockIdx.x*(B_*C2_) + b*C2_ + og*128 + tid] = s2;
    }
#pragma unroll
    for (int it = 0; it < 8; ++it) {
        int l = tid + 256*it;
        int px = l >> 4, seg = l & 15;
        *(int4*)(g_ym + ((size_t)b*P_ + p0 + px)*C2_ + og*128 + seg*8) =
            *(const int4*)&u.outb[px*136 + seg*8];
    }
}

// ---------------------------------------------------------------------------
// K2: finalize stats + fused attention (one block per sample)
// ---------------------------------------------------------------------------
__global__ __launch_bounds__(256)
void k2_fin(const float* __restrict__ fc1w, const float* __restrict__ fc1b,
            const float* __restrict__ fc2w, const float* __restrict__ fc2b)
{
    __shared__ float pooled[256];
    const int b = blockIdx.x, o = threadIdx.x;
    const int idx = b*C2_ + o;
    float s = 0.f, s2 = 0.f;
    for (int t = 0; t < 50; ++t) {
        s  += g_ps [t*(B_*C2_) + idx];
        s2 += g_ps2[t*(B_*C2_) + idx];
    }
    float mu  = s  * (1.f / P_);
    float var = s2 * (1.f / P_) - mu*mu;
    float rs  = rsqrtf(fmaxf(var, 0.f) + EPS_);
    g_mu[idx]   = mu;
    g_rstd[idx] = rs;
    pooled[o] = mu;
    __syncthreads();

    if (o < 32) {
        const int lane = o;
        float s0 = 0.f, s1 = 0.f, s2a = 0.f, s3 = 0.f;
        for (int c = lane; c < C2_; c += 32) {
            float pv = pooled[c];
            s0  += pv * fc1w[0*C2_ + c];
            s1  += pv * fc1w[1*C2_ + c];
            s2a += pv * fc1w[2*C2_ + c];
            s3  += pv * fc1w[3*C2_ + c];
        }
#pragma unroll
        for (int off = 16; off; off >>= 1) {
            s0  += __shfl_down_sync(0xffffffffu, s0,  off);
            s1  += __shfl_down_sync(0xffffffffu, s1,  off);
            s2a += __shfl_down_sync(0xffffffffu, s2a, off);
            s3  += __shfl_down_sync(0xffffffffu, s3,  off);
        }
        if (lane == 0) {
            float a[4];
            a[0] = fmaxf(s0  + fc1b[0], 0.f);
            a[1] = fmaxf(s1  + fc1b[1], 0.f);
            a[2] = fmaxf(s2a + fc1b[2], 0.f);
            a[3] = fmaxf(s3  + fc1b[3], 0.f);
            float l[4];
#pragma unroll
            for (int j = 0; j < 4; ++j)
                l[j] = a[0]*fc2w[j*4+0] + a[1]*fc2w[j*4+1] + a[2]*fc2w[j*4+2] + a[3]*fc2w[j*4+3] + fc2b[j];
            float m = fmaxf(fmaxf(l[0], l[1]), fmaxf(l[2], l[3]));
            float e[4], den = 0.f;
#pragma unroll
            for (int j = 0; j < 4; ++j) { e[j] = expf(l[j] - m); den += e[j]; }
            float inv = 1.f / den;
#pragma unroll
            for (int j = 0; j < 4; ++j) g_attn[b*4 + j] = e[j] * inv;
        }
    }
}

// ---------------------------------------------------------------------------
// K4 v2: aggregate weights, fold rstd, emit k5 A layout.
// Block = (ch=8ci, og, b-group of 8). Stage the 4 dyw banks for a 32-o
// sub-tile ONCE in smem, reuse across 8 samples (16x less dyw traffic).
// ---------------------------------------------------------------------------
__global__ __launch_bounds__(256)
void k4_aggw(const float* __restrict__ dyw)
{
    __shared__ float raw[4][2304];     // [bank][o32*72 + r], 36.9 KB
    const int ch = blockIdx.x, og = blockIdx.y, bg = blockIdx.z;
    const int tid = threadIdx.x;
    const size_t ks = (size_t)C2_*C2_*9;

    for (int og_o = 0; og_o < 4; ++og_o) {
        __syncthreads();               // protect raw reuse across iterations
        // load 4 banks x (32 o x 72 r), coalesced over r
#pragma unroll
        for (int i = 0; i < 9; ++i) {
            int idx = tid + 256*i;     // < 2304
            int o = idx / 72, r = idx - o*72;
            size_t base = (size_t)(og*128 + og_o*32 + o)*2304 + ch*72 + r;
            raw[0][idx] = dyw[base];
            raw[1][idx] = dyw[base + ks];
            raw[2][idx] = dyw[base + 2*ks];
            raw[3][idx] = dyw[base + 3*ks];
        }
        __syncthreads();

        for (int bl = 0; bl < 8; ++bl) {
            const int b = bg*8 + bl;
            const float a0 = __ldg(&g_attn[b*4+0]), a1 = __ldg(&g_attn[b*4+1]);
            const float a2 = __ldg(&g_attn[b*4+2]), a3 = __ldg(&g_attn[b*4+3]);
            float rs[8];
#pragma unroll
            for (int cs = 0; cs < 8; ++cs)
                rs[cs] = __ldg(&g_rstd[b*C2_ + ch*8 + cs]);

            __half* obase = g_wm
                + ((size_t)(b*2 + og)*K5_CH + (ch>>1))*(size_t)(128*K5_K)
                + (ch&1)*8;
            // 288 items: o(32) x q(9), q fast-varying for contiguous write runs
            for (int idx = tid; idx < 288; idx += 256) {
                int o = idx / 9, q = idx - o*9;
                alignas(16) __half hv[8];
#pragma unroll
                for (int cs = 0; cs < 8; ++cs) {
                    float v = a0*raw[0][o*72 + cs*9 + q]
                            + a1*raw[1][o*72 + cs*9 + q]
                            + a2*raw[2][o*72 + cs*9 + q]
                            + a3*raw[3][o*72 + cs*9 + q];
                    v *= rs[cs];
                    hv[cs] = __float2half_rn(v);
                }
                *(int4*)(obase + (size_t)(og_o*32 + o)*K5_K + q*16) = *(const int4*)hv;
            }
        }
    }
}

// K4c: Cq[b,o,q] from the fp16 aggregated weights (rstd folded) + Cqt + agg_b
__global__ __launch_bounds__(288)
void k4c_cq(const float* __restrict__ dyb)
{
    __shared__ float sh[32][9];
    __shared__ float shc[9];
    const int o = blockIdx.x, b = blockIdx.y;
    const int tid = threadIdx.x;
    const int ciw = tid / 9, q = tid - ciw*9;
    const int og = o >> 7, ol = o & 127;

    float acc = 0.f;
    if (tid < 288) {
        const __half* wb = g_wm + (size_t)(b*2 + og)*K5_CH*(size_t)(128*K5_K)
                         + (size_t)ol*K5_K + q*16;
#pragma unroll
        for (int j = 0; j < 8; ++j) {
            int ci = ciw + 32*j;
            int ch = ci >> 4, sub = ci & 15;
            acc += __half2float(wb[(size_t)ch*(128*K5_K) + sub]) * g_mu[b*C2_ + ci];
        }
    }
    sh[ciw][q] = acc;
    __syncthreads();
    if (tid < 9) {
        float sum = 0.f;
#pragma unroll
        for (int i = 0; i < 32; ++i) sum += sh[i][tid];
        g_cq[(b*C2_+o)*9 + tid] = sum;
        shc[tid] = sum;
    }
    __syncthreads();
    if (tid == 0) {
        float sum = 0.f;
#pragma unroll
        for (int i = 0; i < 9; ++i) sum += shc[i];
        g_cqt[b*C2_+o] = sum;
        const float a0 = g_attn[b*4+0], a1 = g_attn[b*4+1];
        const float a2 = g_attn[b*4+2], a3 = g_attn[b*4+3];
        g_aggb[b*C2_+o] = a0*dyb[0*C2_+o] + a1*dyb[1*C2_+o]
                        + a2*dyb[2*C2_+o] + a3*dyb[3*C2_+o];
    }
}

// ---------------------------------------------------------------------------
// K5: implicit-GEMM 3x3 conv, 1-pass fp16 mma.sync (measured-best config:
// 256 threads/CTA -> 2 CTAs/SM resident = 4 warps/SMSP + cross-CTA overlap).
// K = 16 chunks x (9 taps x 16 ci) -> 144 k16-steps (minimum MMA count).
// Block: (b, og, 8x16-px tile). 8 warps = 4M x 2N.
// ---------------------------------------------------------------------------
__global__ __launch_bounds__(256)
void k5_mma(const float* __restrict__ g1, const float* __restrict__ b1,
            const float* __restrict__ m1, const float* __restrict__ v1,
            float* __restrict__ out)
{
    extern __shared__ __align__(16) __half sm5[];
    __half* const As = sm5;                 // [128][ACH=152]
    __half* const Bs = sm5 + 128*ACH;       // [180][BROW=40]

    const int b    = blockIdx.z;
    const int og   = blockIdx.y;
    const int tile = blockIdx.x;                 // 0..49
    const int h0 = (tile/5)*8, w0 = (tile%5)*16;
    const int tid  = threadIdx.x;
    const int lane = tid & 31, warp = tid >> 5;
    const int warp_m = warp & 3, warp_n = warp >> 2;

    float acc[2][8][4];
#pragma unroll
    for (int mr = 0; mr < 2; ++mr)
#pragma unroll
        for (int nr = 0; nr < 8; ++nr)
#pragma unroll
            for (int j = 0; j < 4; ++j) acc[mr][nr][j] = 0.f;

    const __half* wsrc = g_wm + (size_t)(b*2 + og)*K5_CH*(size_t)(128*K5_K);

    // B staging: threads 0..179, one halo pixel each (10x18 halo), 16 ci = 2 int4
    const int st_px = tid;
    const int st_r = st_px/18, st_c = st_px - st_r*18;
    const int gh = h0 + st_r - 1, gw = w0 + st_c - 1;
    const bool st_ok = (tid < 180) && gh >= 0 && gh < H_ && gw >= 0 && gw < W_;
    const int ghc = max(0, min(H_-1, gh)), gwc = max(0, min(W_-1, gw));
    const size_t st_src0 = ((size_t)b*P_ + ghc*W_ + gwc)*(size_t)C2_;

    for (int ch = 0; ch < K5_CH; ++ch) {
        // stage A: 128 o x 144 k (36.9KB) -> rows restrided to ACH
        {
            const int4* asrc = (const int4*)(wsrc + (size_t)ch*(128*K5_K));
            int4* adst = (int4*)As;
#pragma unroll
            for (int i = 0; i < 9; ++i) {
                int idx = tid + 256*i;            // < 2304
                int o = idx / 18, j = idx - o*18;
                adst[o*19 + j] = asrc[idx];
            }
        }
        // stage B: halo pixels x 16 ci of this chunk
        if (tid < 180) {
            int4 v0 = make_int4(0,0,0,0), v1 = make_int4(0,0,0,0);
            if (st_ok) {
                const int4* src = (const int4*)(g_ym + st_src0 + ch*16);
                v0 = src[0]; v1 = src[1];
            }
            *(int4*)&Bs[st_px*BROW]     = v0;
            *(int4*)&Bs[st_px*BROW + 8] = v1;
        }
        __syncthreads();

#pragma unroll
        for (int s = 0; s < 9; ++s) {             // s = tap q
            const int dy = s/3, dx = s - (s/3)*3; // 0..2
            uint32_t ah[2][4];
            const int kb = s*16 + 2*(lane&3);
#pragma unroll
            for (int mr = 0; mr < 2; ++mr) {
                int o = warp_m*32 + mr*16 + (lane>>2);
                const uint32_t* ph  = (const uint32_t*)&As[o*ACH + kb];
                const uint32_t* ph8 = (const uint32_t*)&As[(o+8)*ACH + kb];
                ah[mr][0] = ph[0];  ah[mr][1] = ph8[0];  ah[mr][2] = ph[4];  ah[mr][3] = ph8[4];
            }
            uint32_t bh[8][2];
#pragma unroll
            for (int nr = 0; nr < 8; ++nr) {
                int pr = warp_n*4 + (nr>>1);
                int pc = (nr&1)*8 + (lane>>2);
                const uint32_t* q32 =
                    (const uint32_t*)&Bs[((pr+dy)*18 + pc+dx)*BROW + 2*(lane&3)];
                bh[nr][0] = q32[0];
                bh[nr][1] = q32[4];
            }
#pragma unroll
            for (int mr = 0; mr < 2; ++mr)
#pragma unroll
                for (int nr = 0; nr < 8; ++nr)
                    mma16816(acc[mr][nr], ah[mr], bh[nr]);
        }
        __syncthreads();
    }

    // Epilogue: res = (acc + borderfix)*s + ((aggb - Cqt - m1)*s + b1)
    const int obase = og*128 + warp_m*32;
#pragma unroll
    for (int mr = 0; mr < 2; ++mr) {
        const int o_a = obase + mr*16 + (lane>>2);
        const int o_b = o_a + 8;
        float sA = __ldg(&g1[o_a]) * rsqrtf(__ldg(&v1[o_a]) + EPS_);
        float offA = (__ldg(&g_aggb[b*C2_+o_a]) - g_cqt[b*C2_+o_a] - __ldg(&m1[o_a]))*sA + __ldg(&b1[o_a]);
        float sB = __ldg(&g1[o_b]) * rsqrtf(__ldg(&v1[o_b]) + EPS_);
        float offB = (__ldg(&g_aggb[b*C2_+o_b]) - g_cqt[b*C2_+o_b] - __ldg(&m1[o_b]))*sB + __ldg(&b1[o_b]);
#pragma unroll
        for (int nr = 0; nr < 8; ++nr) {
            int pr = warp_n*4 + (nr>>1);
            int pc = (nr&1)*8 + 2*(lane&3);
            int h = h0 + pr, w1 = w0 + pc, w2 = w1 + 1;
            float fA1 = 0.f, fA2 = 0.f, fB1 = 0.f, fB2 = 0.f;
            if (h == 0 || h == H_-1 || w1 == 0 || w2 == W_-1) {
#pragma unroll
                for (int q = 0; q < 9; ++q) {
                    int dy = q/3 - 1, dx = q - (q/3)*3 - 1;
                    bool ro = (unsigned)(h+dy) >= (unsigned)H_;
                    bool c1 = ro || (unsigned)(w1+dx) >= (unsigned)W_;
                    bool c2 = ro || (unsigned)(w2+dx) >= (unsigned)W_;
                    if (c1 | c2) {
                        float ca = g_cq[(b*C2_+o_a)*9 + q];
                        float cb = g_cq[(b*C2_+o_b)*9 + q];
                        if (c1) { fA1 += ca; fB1 += cb; }
                        if (c2) { fA2 += ca; fB2 += cb; }
                    }
                }
            }
            size_t po = (size_t)h*W_ + w1;
            float2 vA, vB;
            vA.x = (acc[mr][nr][0]+fA1)*sA + offA;  vA.y = (acc[mr][nr][1]+fA2)*sA + offA;
            vB.x = (acc[mr][nr][2]+fB1)*sB + offB;  vB.y = (acc[mr][nr][3]+fB2)*sB + offB;
            *(float2*)&out[((size_t)(b*C2_+o_a))*P_ + po] = vA;
            *(float2*)&out[((size_t)(b*C2_+o_b))*P_ + po] = vB;
        }
    }
}

// ---------------------------------------------------------------------------
extern "C" void kernel_launch(void* const* d_in, const int* in_sizes, int n_in,
                              void* d_out, int out_size)
{
    const float* x      = (const float*)d_in[0];
    const float* conv1w = (const float*)d_in[1];
    const float* bng    = (const float*)d_in[2];
    const float* bnb    = (const float*)d_in[3];
    const float* bnm    = (const float*)d_in[4];
    const float* bnv    = (const float*)d_in[5];
    const float* fc1w   = (const float*)d_in[6];
    const float* fc1b   = (const float*)d_in[7];
    const float* fc2w   = (const float*)d_in[8];
    const float* fc2b   = (const float*)d_in[9];
    const float* dyw    = (const float*)d_in[10];
    const float* dyb    = (const float*)d_in[11];
    const float* g1     = (const float*)d_in[12];
    const float* b1     = (const float*)d_in[13];
    const float* m1     = (const float*)d_in[14];
    const float* v1     = (const float*)d_in[15];
    float* out = (float*)d_out;

    cudaFuncSetAttribute(k5_mma, cudaFuncAttributeMaxDynamicSharedMemorySize, K5_SMEM);

    k1_mma<<<dim3(50, 2, B_), 256>>>(x, conv1w, bng, bnb, bnm, bnv);
    k2_fin<<<B_, 256>>>(fc1w, fc1b, fc2w, fc2b);
    k4_aggw<<<dim3(32, 2, 2), 256>>>(dyw);
    k4c_cq<<<dim3(C2_, B_), 288>>>(dyb);
    k5_mma<<<dim3(50, 2, B_), 256, K5_SMEM>>>(g1, b1, m1, v1, out);
}